// round 10
// baseline (speedup 1.0000x reference)
#include <cuda_runtime.h>
#include <cuda_bf16.h>
#include <cstdint>

// ============================ problem constants ============================
#define NROWS   8192
#define DDIM    128
#define NVIEWS  3
#define TILE_N  128
#define TILE_M  64
#define NCHUNK  16                      // m-range split -> grid 16 x 64 = 1024 CTAs
#define TPC     (NROWS / NCHUNK / TILE_M)   // 8 m-tiles per CTA
#define NSLOT   (NCHUNK * 2)            // partial-denom slots (chunk x warp_m)
#define NTHREADS 512                    // 16 warps: 8(n) x 2(m)

// SMEM layout
#define APITCH  272                     // bytes/row A,B tiles (136 bf16)
#define SPITCHW 72                      // S pitch in floats (conflict-free epilogue)
#define SPITCHB (SPITCHW * 4)           // 288 B
#define SM_A    0
#define A_BYTES (TILE_N * APITCH)               // 34816
#define SM_B    A_BYTES
#define BVIEW   (TILE_M * APITCH)               // 17408 per view
#define SM_S    (SM_B + NVIEWS * BVIEW)         // 87040
#define SBUF    (TILE_N * SPITCHB)              // 36864 per buffer
#define SMEM_BYTES (SM_S + 2 * SBUF)            // 160768

// ============================ device scratch ===============================
__device__ __nv_bfloat16 g_A[NROWS * DDIM];
__device__ __nv_bfloat16 g_B[NVIEWS * NROWS * DDIM];
__device__ float g_partial[NSLOT * NVIEWS * NROWS];   // [slot][v][n]
__device__ float g_bsum[96];

// ============================ ptx helpers ==================================
__device__ __forceinline__ uint32_t smem_u32(const void* p) {
    uint32_t a;
    asm("{ .reg .u64 t; cvta.to.shared.u64 t, %1; cvt.u32.u64 %0, t; }"
        : "=r"(a) : "l"(p));
    return a;
}

__device__ __forceinline__ void cp_async16(uint32_t dst, const void* src) {
    asm volatile("cp.async.cg.shared.global [%0], [%1], 16;"
                 :: "r"(dst), "l"(src) : "memory");
}
#define CP_COMMIT() asm volatile("cp.async.commit_group;" ::: "memory")
#define CP_WAIT(n)  asm volatile("cp.async.wait_group %0;" :: "n"(n) : "memory")

__device__ __forceinline__ void ldmatrix_x4(uint32_t* r, uint32_t addr) {
    asm volatile("ldmatrix.sync.aligned.m8n8.x4.shared.b16 {%0,%1,%2,%3}, [%4];"
                 : "=r"(r[0]), "=r"(r[1]), "=r"(r[2]), "=r"(r[3]) : "r"(addr));
}

__device__ __forceinline__ void mma_16816(float* d, const uint32_t* a,
                                          uint32_t b0, uint32_t b1) {
    asm volatile(
        "mma.sync.aligned.m16n8k16.row.col.f32.bf16.bf16.f32 "
        "{%0,%1,%2,%3}, {%4,%5,%6,%7}, {%8,%9}, {%0,%1,%2,%3};"
        : "+f"(d[0]), "+f"(d[1]), "+f"(d[2]), "+f"(d[3])
        : "r"(a[0]), "r"(a[1]), "r"(a[2]), "r"(a[3]), "r"(b0), "r"(b1));
}

// ===== tiny pad kernels (keep 6-launch pattern so ncu lands on sgcl_main) ==
__global__ void prof_pad1() { if (blockIdx.x == 1) g_bsum[0] = 0.f; }
__global__ void prof_pad2() { if (blockIdx.x == 1) g_bsum[1] = 0.f; }

// ============================ kernel 1: normalize ==========================
__global__ __launch_bounds__(256) void normalize_kernel(
    const float* __restrict__ Hc, const float* __restrict__ Hv) {
    int w = (blockIdx.x * blockDim.x + threadIdx.x) >> 5;   // one warp per row
    int lane = threadIdx.x & 31;
    if (w >= 4 * NROWS) return;
    const float* src;
    __nv_bfloat16* dst;
    if (w < NROWS) { src = Hc + (size_t)w * DDIM;              dst = g_A + (size_t)w * DDIM; }
    else { size_t r = (size_t)(w - NROWS); src = Hv + r * DDIM; dst = g_B + r * DDIM; }

    float4 x = ((const float4*)src)[lane];
    float s = x.x * x.x + x.y * x.y + x.z * x.z + x.w * x.w;
#pragma unroll
    for (int o = 16; o; o >>= 1) s += __shfl_xor_sync(0xFFFFFFFFu, s, o);
    float inv = 1.0f / fmaxf(sqrtf(s), 1e-12f);

    __nv_bfloat162 lo = __floats2bfloat162_rn(x.x * inv, x.y * inv);
    __nv_bfloat162 hi = __floats2bfloat162_rn(x.z * inv, x.w * inv);
    uint2 pk;
    pk.x = *(uint32_t*)&lo;
    pk.y = *(uint32_t*)&hi;
    ((uint2*)dst)[lane] = pk;
}

// ============================ kernel 2: fused GEMM + weighted-exp denoms ===
// 512 thr = 16 warps (8n x 2m) -> 4 warps/SMSP for latency hiding.
// Warp tile 16n x 32m; A fragments (fi=1) hoisted to 32 regs.
__global__ __launch_bounds__(NTHREADS, 1) void sgcl_main(const float* __restrict__ S) {
    extern __shared__ __align__(1024) char smem[];
    const uint32_t sbase = smem_u32(smem);
    const int tid = threadIdx.x, lane = tid & 31, wid = tid >> 5;
    const int warp_n = wid & 7, warp_m = wid >> 3;
    const int chunk = blockIdx.x;
    const int n0 = blockIdx.y * TILE_N;
    const int m_base = chunk * TPC * TILE_M;

    // ---- prefetch S tile 0 ----
    {
        const float* src = S + (size_t)n0 * NROWS + m_base;
#pragma unroll
        for (int t = 0; t < 4; t++) {
            int i = tid + t * NTHREADS;            // 2048 x 16B
            int row = i >> 4, c = i & 15;
            cp_async16(sbase + SM_S + row * SPITCHB + c * 16,
                       src + (size_t)row * NROWS + c * 4);
        }
        CP_COMMIT();
    }

    // ---- stage A tile (once) ----
    {
        const uint4* src = (const uint4*)(g_A + (size_t)n0 * DDIM);
#pragma unroll
        for (int t = 0; t < 4; t++) {
            int i = tid + t * NTHREADS;            // 2048 x 16B
            int row = i >> 4, c = i & 15;
            *(uint4*)(smem + SM_A + row * APITCH + c * 16) = src[i];
        }
    }
    __syncthreads();

    // ---- hoist A fragments (16n x full K): 32 regs ----
    uint32_t a_frag[8][4];
    {
        uint32_t aBase = sbase + SM_A +
            (uint32_t)(warp_n * 16 + (lane & 15)) * APITCH + (uint32_t)(lane >> 4) * 16;
#pragma unroll
        for (int ks = 0; ks < 8; ks++) ldmatrix_x4(a_frag[ks], aBase + ks * 32);
    }

    // B ldmatrix per-lane base (view 0; other views add v*BVIEW)
    const uint32_t bBase0 = sbase + SM_B +
        (uint32_t)(warp_m * 32 + ((lane >> 4) << 3) + (lane & 7)) * APITCH +
        (uint32_t)((lane >> 3) & 1) * 16;

    float accv[NVIEWS][2];
#pragma unroll
    for (int v = 0; v < NVIEWS; v++) { accv[v][0] = 0.f; accv[v][1] = 0.f; }

    for (int mt = 0; mt < TPC; mt++) {
        const int m0 = m_base + mt * TILE_M;
        __syncthreads();   // all warps done with tile mt-1 (B + both S buffers safe)

        if (mt + 1 < TPC) {    // prefetch next S tile
            const float* src = S + (size_t)n0 * NROWS + (m0 + TILE_M);
            uint32_t dstb = sbase + SM_S + (uint32_t)((mt + 1) & 1) * SBUF;
#pragma unroll
            for (int t = 0; t < 4; t++) {
                int i = tid + t * NTHREADS;
                int row = i >> 4, c = i & 15;
                cp_async16(dstb + row * SPITCHB + c * 16,
                           src + (size_t)row * NROWS + c * 4);
            }
            CP_COMMIT();
        }

        // stage B tiles for ALL 3 views (64 rows x 128 bf16 each)
        {
#pragma unroll
            for (int t = 0; t < 6; t++) {
                int i = tid + t * NTHREADS;        // 3072 x 16B
                int view = i >> 10, r = (i >> 4) & 63, c = i & 15;
                const uint4* src = (const uint4*)(g_B +
                    ((size_t)view * NROWS + m0 + r) * DDIM);
                *(uint4*)(smem + SM_B + view * BVIEW + r * APITCH + c * 16) = src[c];
            }
        }
        if (mt + 1 < TPC) CP_WAIT(1); else CP_WAIT(0);
        __syncthreads();   // B staged + S(mt) visible

        const float* sS = (const float*)(smem + SM_S + (size_t)(mt & 1) * SBUF);

#pragma unroll
        for (int v = 0; v < NVIEWS; v++) {
            // ---- 16n x 32m x 128k per warp, register accumulators ----
            float acc[4][4];
#pragma unroll
            for (int mi = 0; mi < 4; mi++)
#pragma unroll
                for (int r = 0; r < 4; r++) acc[mi][r] = 0.0f;

            const uint32_t bV = bBase0 + (uint32_t)v * BVIEW;
#pragma unroll
            for (int ks = 0; ks < 8; ks++) {
                uint32_t b0[4], b1[4];
                ldmatrix_x4(b0, bV + ks * 32);
                ldmatrix_x4(b1, bV + 16 * APITCH + ks * 32);
                mma_16816(acc[0], a_frag[ks], b0[0], b0[1]);
                mma_16816(acc[1], a_frag[ks], b0[2], b0[3]);
                mma_16816(acc[2], a_frag[ks], b1[0], b1[1]);
                mma_16816(acc[3], a_frag[ks], b1[2], b1[3]);
            }

            // ---- fused epilogue: accv += (1 - S) * exp(sim / 0.5) ----
            const float* pA = sS +
                (size_t)(warp_n * 16 + (lane >> 2)) * SPITCHW +
                warp_m * 32 + 2 * (lane & 3);
            const float* pB = pA + 8 * SPITCHW;
            float sA = 0.0f, sB = 0.0f;
#pragma unroll
            for (int mi = 0; mi < 4; mi++) {
                float2 wA = *(const float2*)(pA + mi * 8);
                float2 wB = *(const float2*)(pB + mi * 8);
                const float* d = acc[mi];
                sA += (1.0f - wA.x) * __expf(2.0f * d[0]) +
                      (1.0f - wA.y) * __expf(2.0f * d[1]);
                sB += (1.0f - wB.x) * __expf(2.0f * d[2]) +
                      (1.0f - wB.y) * __expf(2.0f * d[3]);
            }
            accv[v][0] += sA;
            accv[v][1] += sB;
        }
    }

    // ---- quad-reduce, write partial denominators ----
#pragma unroll
    for (int v = 0; v < NVIEWS; v++)
#pragma unroll
        for (int r = 0; r < 2; r++) {
            float val = accv[v][r];
            val += __shfl_xor_sync(0xFFFFFFFFu, val, 1);
            val += __shfl_xor_sync(0xFFFFFFFFu, val, 2);
            if ((lane & 3) == 0) {
                int nl = warp_n * 16 + (lane >> 2) + r * 8;
                g_partial[((chunk * 2 + warp_m) * NVIEWS + v) * NROWS + n0 + nl] = val;
            }
        }
}

// ============================ kernel 3: positive + loss + block partials ===
__global__ __launch_bounds__(256) void posloss_kernel() {
    __shared__ float sm[256];
    int idx = blockIdx.x * 256 + threadIdx.x;      // < 24576
    int v = idx / NROWS, n = idx % NROWS;

    const uint4* pa = (const uint4*)(g_A + (size_t)n * DDIM);
    const uint4* pb = (const uint4*)(g_B + ((size_t)v * NROWS + n) * DDIM);
    float d = 0.f;
#pragma unroll
    for (int i = 0; i < 16; i++) {
        uint4 ua = pa[i], ub = pb[i];
        const __nv_bfloat162* xa = (const __nv_bfloat162*)&ua;
        const __nv_bfloat162* xb = (const __nv_bfloat162*)&ub;
#pragma unroll
        for (int j = 0; j < 4; j++) {
            float2 a = __bfloat1622float2(xa[j]);
            float2 b = __bfloat1622float2(xb[j]);
            d += a.x * b.x + a.y * b.y;
        }
    }
    float denom = 0.f;
#pragma unroll
    for (int p = 0; p < NSLOT; p++)
        denom += g_partial[(p * NVIEWS + v) * NROWS + n];
    denom = fmaxf(denom, 1e-9f);
    float loss = logf(denom) - 2.0f * d;           // -(pos - log denom)

    sm[threadIdx.x] = loss;
    __syncthreads();
#pragma unroll
    for (int st = 128; st; st >>= 1) {
        if (threadIdx.x < st) sm[threadIdx.x] += sm[threadIdx.x + st];
        __syncthreads();
    }
    if (threadIdx.x == 0) g_bsum[blockIdx.x] = sm[0];
}

// ============================ kernel 4: final tiny reduce ==================
__global__ void final_reduce(float* __restrict__ out) {
    int lane = threadIdx.x;
    float s = 0.f;
    for (int i = lane; i < 96; i += 32) s += g_bsum[i];
#pragma unroll
    for (int o = 16; o; o >>= 1) s += __shfl_xor_sync(0xFFFFFFFFu, s, o);
    if (lane == 0) out[0] = s * (1.0f / (NVIEWS * NROWS));
}

// ============================ launch =======================================
extern "C" void kernel_launch(void* const* d_in, const int* in_sizes, int n_in,
                              void* d_out, int out_size) {
    const float* Hc = (const float*)d_in[0];
    const float* S  = (const float*)d_in[1];
    const float* Hv = (const float*)d_in[2];

    cudaFuncSetAttribute(sgcl_main, cudaFuncAttributeMaxDynamicSharedMemorySize,
                         SMEM_BYTES);

    prof_pad1<<<1, 32>>>();
    prof_pad2<<<1, 32>>>();
    normalize_kernel<<<(4 * NROWS) / 8, 256>>>(Hc, Hv);
    sgcl_main<<<dim3(NCHUNK, NROWS / TILE_N), NTHREADS, SMEM_BYTES>>>(S);
    posloss_kernel<<<96, 256>>>();
    final_reduce<<<1, 32>>>((float*)d_out);
}

// round 11
// speedup vs baseline: 1.5090x; 1.5090x over previous
#include <cuda_runtime.h>
#include <cuda_bf16.h>
#include <cstdint>

// ============================ problem constants ============================
#define NROWS   8192
#define DDIM    128
#define NVIEWS  3
#define TILE_N  128
#define TILE_M  64
#define NCHUNK  16                      // m-range split -> grid 16 x 64 = 1024 CTAs
#define TPC     (NROWS / NCHUNK / TILE_M)   // 8 m-tiles per CTA
#define NSLOT   (NCHUNK * 2)            // partial-denom slots (chunk x warp_m)
#define NTHREADS 256                    // 8 warps: 4(n) x 2(m)  (best-known config)

// SMEM layout
#define APITCH  272                     // bytes/row A,B tiles (136 bf16)
#define SPITCHW 72                      // S pitch in floats (conflict-free epilogue)
#define SPITCHB (SPITCHW * 4)           // 288 B
#define SM_A    0
#define A_BYTES (TILE_N * APITCH)               // 34816
#define SM_B    A_BYTES
#define BVIEW   (TILE_M * APITCH)               // 17408 per view
#define B_BUF   (NVIEWS * BVIEW)                // 52224 per buffer
#define SM_S    (SM_B + 2 * B_BUF)              // 139264
#define SBUF    (TILE_N * SPITCHB)              // 36864 per buffer
#define SMEM_BYTES (SM_S + 2 * SBUF)            // 212992

// ============================ device scratch ===============================
__device__ __nv_bfloat16 g_A[NROWS * DDIM];
__device__ __nv_bfloat16 g_B[NVIEWS * NROWS * DDIM];
__device__ float g_partial[NSLOT * NVIEWS * NROWS];   // [slot][v][n]
__device__ float g_bsum[96];

// ============================ ptx helpers ==================================
__device__ __forceinline__ uint32_t smem_u32(const void* p) {
    uint32_t a;
    asm("{ .reg .u64 t; cvta.to.shared.u64 t, %1; cvt.u32.u64 %0, t; }"
        : "=r"(a) : "l"(p));
    return a;
}

__device__ __forceinline__ void cp_async16(uint32_t dst, const void* src) {
    asm volatile("cp.async.cg.shared.global [%0], [%1], 16;"
                 :: "r"(dst), "l"(src) : "memory");
}
#define CP_COMMIT() asm volatile("cp.async.commit_group;" ::: "memory")
#define CP_WAIT(n)  asm volatile("cp.async.wait_group %0;" :: "n"(n) : "memory")

__device__ __forceinline__ void ldmatrix_x4(uint32_t* r, uint32_t addr) {
    asm volatile("ldmatrix.sync.aligned.m8n8.x4.shared.b16 {%0,%1,%2,%3}, [%4];"
                 : "=r"(r[0]), "=r"(r[1]), "=r"(r[2]), "=r"(r[3]) : "r"(addr));
}

__device__ __forceinline__ void mma_16816(float* d, const uint32_t* a,
                                          uint32_t b0, uint32_t b1) {
    asm volatile(
        "mma.sync.aligned.m16n8k16.row.col.f32.bf16.bf16.f32 "
        "{%0,%1,%2,%3}, {%4,%5,%6,%7}, {%8,%9}, {%0,%1,%2,%3};"
        : "+f"(d[0]), "+f"(d[1]), "+f"(d[2]), "+f"(d[3])
        : "r"(a[0]), "r"(a[1]), "r"(a[2]), "r"(a[3]), "r"(b0), "r"(b1));
}

// ===== tiny pad kernels (keep 6-launch pattern so ncu lands on sgcl_main) ==
__global__ void prof_pad1() { if (blockIdx.x == 1) g_bsum[0] = 0.f; }
__global__ void prof_pad2() { if (blockIdx.x == 1) g_bsum[1] = 0.f; }

// ============================ kernel 1: normalize ==========================
__global__ __launch_bounds__(256) void normalize_kernel(
    const float* __restrict__ Hc, const float* __restrict__ Hv) {
    int w = (blockIdx.x * blockDim.x + threadIdx.x) >> 5;   // one warp per row
    int lane = threadIdx.x & 31;
    if (w >= 4 * NROWS) return;
    const float* src;
    __nv_bfloat16* dst;
    if (w < NROWS) { src = Hc + (size_t)w * DDIM;              dst = g_A + (size_t)w * DDIM; }
    else { size_t r = (size_t)(w - NROWS); src = Hv + r * DDIM; dst = g_B + r * DDIM; }

    float4 x = ((const float4*)src)[lane];
    float s = x.x * x.x + x.y * x.y + x.z * x.z + x.w * x.w;
#pragma unroll
    for (int o = 16; o; o >>= 1) s += __shfl_xor_sync(0xFFFFFFFFu, s, o);
    float inv = 1.0f / fmaxf(sqrtf(s), 1e-12f);

    __nv_bfloat162 lo = __floats2bfloat162_rn(x.x * inv, x.y * inv);
    __nv_bfloat162 hi = __floats2bfloat162_rn(x.z * inv, x.w * inv);
    uint2 pk;
    pk.x = *(uint32_t*)&lo;
    pk.y = *(uint32_t*)&hi;
    ((uint2*)dst)[lane] = pk;
}

// ---- prefetch one full m-tile (S + all 3 views' B) into the given buffers --
__device__ __forceinline__ void prefetch_tile(uint32_t sbase, int tid,
                                              const float* __restrict__ S,
                                              int n0, int m0, int buf) {
    // S tile: 128 rows x 64 floats  (2048 x 16B chunks)
    {
        const float* src = S + (size_t)n0 * NROWS + m0;
        uint32_t dstb = sbase + SM_S + (uint32_t)buf * SBUF;
#pragma unroll
        for (int t = 0; t < 8; t++) {
            int i = tid + t * NTHREADS;
            int row = i >> 4, c = i & 15;
            cp_async16(dstb + row * SPITCHB + c * 16,
                       src + (size_t)row * NROWS + c * 4);
        }
    }
    // B tiles: 3 views x 64 rows x 128 bf16  (3072 x 16B chunks)
    {
        uint32_t dstb = sbase + SM_B + (uint32_t)buf * B_BUF;
#pragma unroll
        for (int t = 0; t < 12; t++) {
            int i = tid + t * NTHREADS;
            int view = i >> 10, r = (i >> 4) & 63, c = i & 15;
            const char* src = (const char*)(g_B +
                ((size_t)view * NROWS + m0 + r) * DDIM) + c * 16;
            cp_async16(dstb + view * BVIEW + r * APITCH + c * 16, src);
        }
    }
    CP_COMMIT();
}

// ============================ kernel 2: fused GEMM + weighted-exp denoms ===
// 256 thr = 8 warps (4n x 2m), warp tile 32n x 64m (best LDSM/FLOP ratio).
// S AND B double-buffered via cp.async (depth-1 pipeline) -> no synchronous
// staging exposure; compute phase is sync-free so warps drift (tensor||MUFU).
__global__ __launch_bounds__(NTHREADS, 1) void sgcl_main(const float* __restrict__ S) {
    extern __shared__ __align__(1024) char smem[];
    const uint32_t sbase = smem_u32(smem);
    const int tid = threadIdx.x, lane = tid & 31, wid = tid >> 5;
    const int warp_n = wid & 3, warp_m = wid >> 2;
    const int chunk = blockIdx.x;
    const int n0 = blockIdx.y * TILE_N;
    const int m_base = chunk * TPC * TILE_M;

    // ---- prefetch tile 0 (S + B, buffer 0) ----
    prefetch_tile(sbase, tid, S, n0, m_base, 0);

    // ---- stage A tile (once, synchronous is fine: one-time cost) ----
    {
        const uint4* src = (const uint4*)(g_A + (size_t)n0 * DDIM);
#pragma unroll
        for (int t = 0; t < 8; t++) {
            int i = tid + t * NTHREADS;            // 2048 x 16B
            int row = i >> 4, c = i & 15;
            *(uint4*)(smem + SM_A + row * APITCH + c * 16) = src[i];
        }
    }
    __syncthreads();

    // ---- hoist A fragments to registers (loop-invariant for whole CTA) ----
    uint32_t a_frag[8][2][4];
    {
        uint32_t aBase0 = sbase + SM_A +
            (uint32_t)(warp_n * 32 + (lane & 15)) * APITCH + (uint32_t)(lane >> 4) * 16;
#pragma unroll
        for (int ks = 0; ks < 8; ks++) {
            ldmatrix_x4(a_frag[ks][0], aBase0 + ks * 32);
            ldmatrix_x4(a_frag[ks][1], aBase0 + 16 * APITCH + ks * 32);
        }
    }

    // B ldmatrix per-lane base (buffer 0, view 0)
    const uint32_t bBase0 = sbase + SM_B +
        (uint32_t)(warp_m * 32 + ((lane >> 4) << 3) + (lane & 7)) * APITCH +
        (uint32_t)((lane >> 3) & 1) * 16;

    float accv[NVIEWS][4];
#pragma unroll
    for (int v = 0; v < NVIEWS; v++)
#pragma unroll
        for (int r = 0; r < 4; r++) accv[v][r] = 0.0f;

    for (int mt = 0; mt < TPC; mt++) {
        const int m0 = m_base + mt * TILE_M;
        __syncthreads();   // all warps done with tile mt-1 -> buffer (mt+1)&1 free

        if (mt + 1 < TPC)  // prefetch next tile's S+B into the freed buffer
            prefetch_tile(sbase, tid, S, n0, m0 + TILE_M, (mt + 1) & 1);

        if (mt + 1 < TPC) CP_WAIT(1); else CP_WAIT(0);   // tile mt arrived
        __syncthreads();   // visible to all warps

        const int buf = mt & 1;
        const float* sS = (const float*)(smem + SM_S + (size_t)buf * SBUF);
        const uint32_t bBufBase = bBase0 + (uint32_t)buf * B_BUF;

#pragma unroll
        for (int v = 0; v < NVIEWS; v++) {
            // ---- 128x64x128 bf16 GEMM, register accumulators ----
            float acc[2][4][4];
#pragma unroll
            for (int fi = 0; fi < 2; fi++)
#pragma unroll
                for (int mi = 0; mi < 4; mi++)
#pragma unroll
                    for (int r = 0; r < 4; r++) acc[fi][mi][r] = 0.0f;

            const uint32_t bV = bBufBase + (uint32_t)v * BVIEW;
#pragma unroll
            for (int ks = 0; ks < 8; ks++) {
                uint32_t b[2][4];
                ldmatrix_x4(b[0], bV + ks * 32);
                ldmatrix_x4(b[1], bV + 16 * APITCH + ks * 32);
#pragma unroll
                for (int fi = 0; fi < 2; fi++)
#pragma unroll
                    for (int bp = 0; bp < 2; bp++)
#pragma unroll
                        for (int t2 = 0; t2 < 2; t2++)
                            mma_16816(acc[fi][bp * 2 + t2], a_frag[ks][fi],
                                      b[bp][2 * t2], b[bp][2 * t2 + 1]);
            }

            // ---- fused epilogue: accv += (1 - S) * exp(sim / 0.5) ----
#pragma unroll
            for (int fi = 0; fi < 2; fi++) {
                const float* pA = sS +
                    (size_t)(warp_n * 32 + fi * 16 + (lane >> 2)) * SPITCHW +
                    warp_m * 32 + 2 * (lane & 3);
                const float* pB = pA + 8 * SPITCHW;
                float sA = 0.0f, sB = 0.0f;
#pragma unroll
                for (int mi = 0; mi < 4; mi++) {
                    float2 wA = *(const float2*)(pA + mi * 8);
                    float2 wB = *(const float2*)(pB + mi * 8);
                    const float* d = acc[fi][mi];
                    sA += (1.0f - wA.x) * __expf(2.0f * d[0]) +
                          (1.0f - wA.y) * __expf(2.0f * d[1]);
                    sB += (1.0f - wB.x) * __expf(2.0f * d[2]) +
                          (1.0f - wB.y) * __expf(2.0f * d[3]);
                }
                accv[v][fi * 2 + 0] += sA;
                accv[v][fi * 2 + 1] += sB;
            }
        }
    }

    // ---- quad-reduce, write partial denominators ----
#pragma unroll
    for (int v = 0; v < NVIEWS; v++)
#pragma unroll
        for (int r = 0; r < 4; r++) {
            float val = accv[v][r];
            val += __shfl_xor_sync(0xFFFFFFFFu, val, 1);
            val += __shfl_xor_sync(0xFFFFFFFFu, val, 2);
            if ((lane & 3) == 0) {
                int nl = warp_n * 32 + (r >> 1) * 16 + (lane >> 2) + (r & 1) * 8;
                g_partial[((chunk * 2 + warp_m) * NVIEWS + v) * NROWS + n0 + nl] = val;
            }
        }
}

// ============================ kernel 3: positive + loss + block partials ===
__global__ __launch_bounds__(256) void posloss_kernel() {
    __shared__ float sm[256];
    int idx = blockIdx.x * 256 + threadIdx.x;      // < 24576
    int v = idx / NROWS, n = idx % NROWS;

    const uint4* pa = (const uint4*)(g_A + (size_t)n * DDIM);
    const uint4* pb = (const uint4*)(g_B + ((size_t)v * NROWS + n) * DDIM);
    float d = 0.f;
#pragma unroll
    for (int i = 0; i < 16; i++) {
        uint4 ua = pa[i], ub = pb[i];
        const __nv_bfloat162* xa = (const __nv_bfloat162*)&ua;
        const __nv_bfloat162* xb = (const __nv_bfloat162*)&ub;
#pragma unroll
        for (int j = 0; j < 4; j++) {
            float2 a = __bfloat1622float2(xa[j]);
            float2 b = __bfloat1622float2(xb[j]);
            d += a.x * b.x + a.y * b.y;
        }
    }
    float denom = 0.f;
#pragma unroll
    for (int p = 0; p < NSLOT; p++)
        denom += g_partial[(p * NVIEWS + v) * NROWS + n];
    denom = fmaxf(denom, 1e-9f);
    float loss = logf(denom) - 2.0f * d;           // -(pos - log denom)

    sm[threadIdx.x] = loss;
    __syncthreads();
#pragma unroll
    for (int st = 128; st; st >>= 1) {
        if (threadIdx.x < st) sm[threadIdx.x] += sm[threadIdx.x + st];
        __syncthreads();
    }
    if (threadIdx.x == 0) g_bsum[blockIdx.x] = sm[0];
}

// ============================ kernel 4: final tiny reduce ==================
__global__ void final_reduce(float* __restrict__ out) {
    int lane = threadIdx.x;
    float s = 0.f;
    for (int i = lane; i < 96; i += 32) s += g_bsum[i];
#pragma unroll
    for (int o = 16; o; o >>= 1) s += __shfl_xor_sync(0xFFFFFFFFu, s, o);
    if (lane == 0) out[0] = s * (1.0f / (NVIEWS * NROWS));
}

// ============================ launch =======================================
extern "C" void kernel_launch(void* const* d_in, const int* in_sizes, int n_in,
                              void* d_out, int out_size) {
    const float* Hc = (const float*)d_in[0];
    const float* S  = (const float*)d_in[1];
    const float* Hv = (const float*)d_in[2];

    cudaFuncSetAttribute(sgcl_main, cudaFuncAttributeMaxDynamicSharedMemorySize,
                         SMEM_BYTES);

    prof_pad1<<<1, 32>>>();
    prof_pad2<<<1, 32>>>();
    normalize_kernel<<<(4 * NROWS) / 8, 256>>>(Hc, Hv);
    sgcl_main<<<dim3(NCHUNK, NROWS / TILE_N), NTHREADS, SMEM_BYTES>>>(S);
    posloss_kernel<<<96, 256>>>();
    final_reduce<<<1, 32>>>((float*)d_out);
}

// round 13
// speedup vs baseline: 1.6879x; 1.1186x over previous
#include <cuda_runtime.h>
#include <cuda_bf16.h>
#include <cstdint>

// ============================ problem constants ============================
#define NROWS   8192
#define DDIM    128
#define NVIEWS  3
#define TILE_N  128
#define TILE_M  64
#define NCHUNK  16                      // m-range split -> grid 16 x 64 = 1024 CTAs
#define TPC     (NROWS / NCHUNK / TILE_M)   // 8 m-tiles per CTA
#define NSLOT   (NCHUNK * 2)            // partial-denom slots (chunk x warp_m)
#define NTHREADS 256                    // 8 warps: 4(n) x 2(m)

// exp(2x) = ex2(x * 2/ln2)
#define EXP2SCALE 2.8853900817779268f

// SMEM layout
#define APITCH  272                     // bytes/row A,B tiles (136 bf16)
#define SPITCHW 72                      // S pitch in floats (conflict-free epilogue)
#define SPITCHB (SPITCHW * 4)           // 288 B
#define SM_A    0
#define A_BYTES (TILE_N * APITCH)               // 34816
#define SM_B    A_BYTES
#define BVIEW   (TILE_M * APITCH)               // 17408 per view
#define B_BUF   (NVIEWS * BVIEW)                // 52224 per buffer
#define SM_S    (SM_B + 2 * B_BUF)              // 139264
#define SBUF    (TILE_N * SPITCHB)              // 36864 per buffer
#define SMEM_BYTES (SM_S + 2 * SBUF)            // 212992

// ============================ device scratch ===============================
__device__ __nv_bfloat16 g_A[NROWS * DDIM];
__device__ __nv_bfloat16 g_B[NVIEWS * NROWS * DDIM];
__device__ float g_partial[NSLOT * NVIEWS * NROWS];   // [slot][v][n]
__device__ float g_bsum[96];

// ============================ ptx helpers ==================================
__device__ __forceinline__ uint32_t smem_u32(const void* p) {
    uint32_t a;
    asm("{ .reg .u64 t; cvta.to.shared.u64 t, %1; cvt.u32.u64 %0, t; }"
        : "=r"(a) : "l"(p));
    return a;
}

__device__ __forceinline__ float fast_ex2(float x) {
    float y;
    asm("ex2.approx.ftz.f32 %0, %1;" : "=f"(y) : "f"(x));
    return y;
}

__device__ __forceinline__ void cp_async16(uint32_t dst, const void* src) {
    asm volatile("cp.async.cg.shared.global [%0], [%1], 16;"
                 :: "r"(dst), "l"(src) : "memory");
}
#define CP_COMMIT() asm volatile("cp.async.commit_group;" ::: "memory")
#define CP_WAIT(n)  asm volatile("cp.async.wait_group %0;" :: "n"(n) : "memory")

__device__ __forceinline__ void ldmatrix_x4(uint32_t* r, uint32_t addr) {
    asm volatile("ldmatrix.sync.aligned.m8n8.x4.shared.b16 {%0,%1,%2,%3}, [%4];"
                 : "=r"(r[0]), "=r"(r[1]), "=r"(r[2]), "=r"(r[3]) : "r"(addr));
}

__device__ __forceinline__ void mma_16816(float* d, const uint32_t* a,
                                          uint32_t b0, uint32_t b1) {
    asm volatile(
        "mma.sync.aligned.m16n8k16.row.col.f32.bf16.bf16.f32 "
        "{%0,%1,%2,%3}, {%4,%5,%6,%7}, {%8,%9}, {%0,%1,%2,%3};"
        : "+f"(d[0]), "+f"(d[1]), "+f"(d[2]), "+f"(d[3])
        : "r"(a[0]), "r"(a[1]), "r"(a[2]), "r"(a[3]), "r"(b0), "r"(b1));
}

// ===== tiny pad kernels (keep 6-launch pattern so ncu lands on sgcl_main) ==
__global__ void prof_pad1() { if (blockIdx.x == 1) g_bsum[0] = 0.f; }
__global__ void prof_pad2() { if (blockIdx.x == 1) g_bsum[1] = 0.f; }

// ============================ kernel 1: normalize ==========================
__global__ __launch_bounds__(256) void normalize_kernel(
    const float* __restrict__ Hc, const float* __restrict__ Hv) {
    int w = (blockIdx.x * blockDim.x + threadIdx.x) >> 5;   // one warp per row
    int lane = threadIdx.x & 31;
    if (w >= 4 * NROWS) return;
    const float* src;
    __nv_bfloat16* dst;
    if (w < NROWS) { src = Hc + (size_t)w * DDIM;              dst = g_A + (size_t)w * DDIM; }
    else { size_t r = (size_t)(w - NROWS); src = Hv + r * DDIM; dst = g_B + r * DDIM; }

    float4 x = ((const float4*)src)[lane];
    float s = x.x * x.x + x.y * x.y + x.z * x.z + x.w * x.w;
#pragma unroll
    for (int o = 16; o; o >>= 1) s += __shfl_xor_sync(0xFFFFFFFFu, s, o);
    float inv = 1.0f / fmaxf(sqrtf(s), 1e-12f);

    __nv_bfloat162 lo = __floats2bfloat162_rn(x.x * inv, x.y * inv);
    __nv_bfloat162 hi = __floats2bfloat162_rn(x.z * inv, x.w * inv);
    uint2 pk;
    pk.x = *(uint32_t*)&lo;
    pk.y = *(uint32_t*)&hi;
    ((uint2*)dst)[lane] = pk;
}

// ---- prefetch one full m-tile (S + all 3 views' B) into the given buffers --
__device__ __forceinline__ void prefetch_tile(uint32_t sbase, int tid,
                                              const float* __restrict__ S,
                                              int n0, int m0, int buf) {
    {
        const float* src = S + (size_t)n0 * NROWS + m0;
        uint32_t dstb = sbase + SM_S + (uint32_t)buf * SBUF;
#pragma unroll
        for (int t = 0; t < 8; t++) {
            int i = tid + t * NTHREADS;
            int row = i >> 4, c = i & 15;
            cp_async16(dstb + row * SPITCHB + c * 16,
                       src + (size_t)row * NROWS + c * 4);
        }
    }
    {
        uint32_t dstb = sbase + SM_B + (uint32_t)buf * B_BUF;
#pragma unroll
        for (int t = 0; t < 12; t++) {
            int i = tid + t * NTHREADS;
            int view = i >> 10, r = (i >> 4) & 63, c = i & 15;
            const char* src = (const char*)(g_B +
                ((size_t)view * NROWS + m0 + r) * DDIM) + c * 16;
            cp_async16(dstb + view * BVIEW + r * APITCH + c * 16, src);
        }
    }
    CP_COMMIT();
}

// ---- one epilogue unit: 4 elements of (1-S)*exp(2*sim) -> accvP[2] --------
__device__ __forceinline__ void epi_unit(const float d[4], const float* epiBase,
                                         int fi, int mi, float* accvP) {
    const float* pA = epiBase + fi * 16 * SPITCHW + mi * 8;
    const float* pB = pA + 8 * SPITCHW;
    float2 wA = *(const float2*)pA;
    float2 wB = *(const float2*)pB;
    accvP[fi * 2 + 0] += (1.0f - wA.x) * fast_ex2(d[0] * EXP2SCALE) +
                         (1.0f - wA.y) * fast_ex2(d[1] * EXP2SCALE);
    accvP[fi * 2 + 1] += (1.0f - wB.x) * fast_ex2(d[2] * EXP2SCALE) +
                         (1.0f - wB.y) * fast_ex2(d[3] * EXP2SCALE);
}

// ---- MMA of one view, with PREVIOUS view's epilogue interleaved by ks -----
// accC: written (zeroed first). accP: consumed if doEpi.
__device__ __forceinline__ void mma_view(
    float accC[2][4][4], uint32_t bV, const uint32_t a_frag[8][2][4],
    bool doEpi, const float accP[2][4][4], const float* epiBase, float* accvP) {
#pragma unroll
    for (int fi = 0; fi < 2; fi++)
#pragma unroll
        for (int mi = 0; mi < 4; mi++)
#pragma unroll
            for (int r = 0; r < 4; r++) accC[fi][mi][r] = 0.0f;

#pragma unroll
    for (int ks = 0; ks < 8; ks++) {
        uint32_t b0[4], b1[4];
        ldmatrix_x4(b0, bV + ks * 32);
        ldmatrix_x4(b1, bV + 16 * APITCH + ks * 32);
#pragma unroll
        for (int fi = 0; fi < 2; fi++) {
            mma_16816(accC[fi][0], a_frag[ks][fi], b0[0], b0[1]);
            mma_16816(accC[fi][1], a_frag[ks][fi], b0[2], b0[3]);
            mma_16816(accC[fi][2], a_frag[ks][fi], b1[0], b1[1]);
            mma_16816(accC[fi][3], a_frag[ks][fi], b1[2], b1[3]);
        }
        // interleaved epilogue chunk of previous view (fills HMMA issue gaps)
        if (doEpi) epi_unit(accP[ks >> 2][ks & 3], epiBase, ks >> 2, ks & 3, accvP);
    }
}

// ---- full (exposed) epilogue of one acc set -------------------------------
__device__ __forceinline__ void epi_full(const float accP[2][4][4],
                                         const float* epiBase, float* accvP) {
#pragma unroll
    for (int fi = 0; fi < 2; fi++)
#pragma unroll
        for (int mi = 0; mi < 4; mi++)
            epi_unit(accP[fi][mi], epiBase, fi, mi, accvP);
}

// ============================ kernel 2: fused GEMM + weighted-exp denoms ===
// 8 warps (4n x 2m), warp tile 32n x 32m. Per m-tile: 3 view-passes with the
// previous view's epilogue interleaved into the current view's MMA ks-loop;
// only the last view's epilogue is exposed (1/3 of previous exposure).
__global__ __launch_bounds__(NTHREADS, 1) void sgcl_main(const float* __restrict__ S) {
    extern __shared__ __align__(1024) char smem[];
    const uint32_t sbase = smem_u32(smem);
    const int tid = threadIdx.x, lane = tid & 31, wid = tid >> 5;
    const int warp_n = wid & 3, warp_m = wid >> 2;
    const int chunk = blockIdx.x;
    const int n0 = blockIdx.y * TILE_N;
    const int m_base = chunk * TPC * TILE_M;

    prefetch_tile(sbase, tid, S, n0, m_base, 0);

    // ---- stage A tile (once) ----
    {
        const uint4* src = (const uint4*)(g_A + (size_t)n0 * DDIM);
#pragma unroll
        for (int t = 0; t < 8; t++) {
            int i = tid + t * NTHREADS;
            int row = i >> 4, c = i & 15;
            *(uint4*)(smem + SM_A + row * APITCH + c * 16) = src[i];
        }
    }
    __syncthreads();

    // ---- hoist A fragments to registers ----
    uint32_t a_frag[8][2][4];
    {
        uint32_t aBase0 = sbase + SM_A +
            (uint32_t)(warp_n * 32 + (lane & 15)) * APITCH + (uint32_t)(lane >> 4) * 16;
#pragma unroll
        for (int ks = 0; ks < 8; ks++) {
            ldmatrix_x4(a_frag[ks][0], aBase0 + ks * 32);
            ldmatrix_x4(a_frag[ks][1], aBase0 + 16 * APITCH + ks * 32);
        }
    }

    const uint32_t bBase0 = sbase + SM_B +
        (uint32_t)(warp_m * 32 + ((lane >> 4) << 3) + (lane & 7)) * APITCH +
        (uint32_t)((lane >> 3) & 1) * 16;

    float accv[NVIEWS][4];
#pragma unroll
    for (int v = 0; v < NVIEWS; v++)
#pragma unroll
        for (int r = 0; r < 4; r++) accv[v][r] = 0.0f;

    float accA[2][4][4], accB[2][4][4];

    for (int mt = 0; mt < TPC; mt++) {
        const int m0 = m_base + mt * TILE_M;
        __syncthreads();   // all warps done with tile mt-1 -> buffer (mt+1)&1 free

        if (mt + 1 < TPC)
            prefetch_tile(sbase, tid, S, n0, m0 + TILE_M, (mt + 1) & 1);

        if (mt + 1 < TPC) CP_WAIT(1); else CP_WAIT(0);
        __syncthreads();

        const int buf = mt & 1;
        const float* sS = (const float*)(smem + SM_S + (size_t)buf * SBUF);
        const float* epiBase = sS +
            (size_t)(warp_n * 32 + (lane >> 2)) * SPITCHW +
            warp_m * 32 + 2 * (lane & 3);
        const uint32_t bBuf = bBase0 + (uint32_t)buf * B_BUF;

        // pass0: MMA v0 -> accA
        mma_view(accA, bBuf + 0 * BVIEW, a_frag, false, accA, epiBase, accv[0]);
        // pass1: MMA v1 -> accB, interleaved epi(accA -> v0)
        mma_view(accB, bBuf + 1 * BVIEW, a_frag, true, accA, epiBase, accv[0]);
        // pass2: MMA v2 -> accA (epi'd already), interleaved epi(accB -> v1)
        mma_view(accA, bBuf + 2 * BVIEW, a_frag, true, accB, epiBase, accv[1]);
        // tail: exposed epi(accA -> v2)
        epi_full(accA, epiBase, accv[2]);
    }

    // ---- quad-reduce, write partial denominators ----
#pragma unroll
    for (int v = 0; v < NVIEWS; v++)
#pragma unroll
        for (int r = 0; r < 4; r++) {
            float val = accv[v][r];
            val += __shfl_xor_sync(0xFFFFFFFFu, val, 1);
            val += __shfl_xor_sync(0xFFFFFFFFu, val, 2);
            if ((lane & 3) == 0) {
                int nl = warp_n * 32 + (r >> 1) * 16 + (lane >> 2) + (r & 1) * 8;
                g_partial[((chunk * 2 + warp_m) * NVIEWS + v) * NROWS + n0 + nl] = val;
            }
        }
}

// ============================ kernel 3: positive + loss + block partials ===
__global__ __launch_bounds__(256) void posloss_kernel() {
    __shared__ float sm[256];
    int idx = blockIdx.x * 256 + threadIdx.x;      // < 24576
    int v = idx / NROWS, n = idx % NROWS;

    const uint4* pa = (const uint4*)(g_A + (size_t)n * DDIM);
    const uint4* pb = (const uint4*)(g_B + ((size_t)v * NROWS + n) * DDIM);
    float d = 0.f;
#pragma unroll
    for (int i = 0; i < 16; i++) {
        uint4 ua = pa[i], ub = pb[i];
        const __nv_bfloat162* xa = (const __nv_bfloat162*)&ua;
        const __nv_bfloat162* xb = (const __nv_bfloat162*)&ub;
#pragma unroll
        for (int j = 0; j < 4; j++) {
            float2 a = __bfloat1622float2(xa[j]);
            float2 b = __bfloat1622float2(xb[j]);
            d += a.x * b.x + a.y * b.y;
        }
    }
    float denom = 0.f;
#pragma unroll
    for (int p = 0; p < NSLOT; p++)
        denom += g_partial[(p * NVIEWS + v) * NROWS + n];
    denom = fmaxf(denom, 1e-9f);
    float loss = logf(denom) - 2.0f * d;           // -(pos - log denom)

    sm[threadIdx.x] = loss;
    __syncthreads();
#pragma unroll
    for (int st = 128; st; st >>= 1) {
        if (threadIdx.x < st) sm[threadIdx.x] += sm[threadIdx.x + st];
        __syncthreads();
    }
    if (threadIdx.x == 0) g_bsum[blockIdx.x] = sm[0];
}

// ============================ kernel 4: final tiny reduce ==================
__global__ void final_reduce(float* __restrict__ out) {
    int lane = threadIdx.x;
    float s = 0.f;
    for (int i = lane; i < 96; i += 32) s += g_bsum[i];
#pragma unroll
    for (int o = 16; o; o >>= 1) s += __shfl_xor_sync(0xFFFFFFFFu, s, o);
    if (lane == 0) out[0] = s * (1.0f / (NVIEWS * NROWS));
}

// ============================ launch =======================================
extern "C" void kernel_launch(void* const* d_in, const int* in_sizes, int n_in,
                              void* d_out, int out_size) {
    const float* Hc = (const float*)d_in[0];
    const float* S  = (const float*)d_in[1];
    const float* Hv = (const float*)d_in[2];

    cudaFuncSetAttribute(sgcl_main, cudaFuncAttributeMaxDynamicSharedMemorySize,
                         SMEM_BYTES);

    prof_pad1<<<1, 32>>>();
    prof_pad2<<<1, 32>>>();
    normalize_kernel<<<(4 * NROWS) / 8, 256>>>(Hc, Hv);
    sgcl_main<<<dim3(NCHUNK, NROWS / TILE_N), NTHREADS, SMEM_BYTES>>>(S);
    posloss_kernel<<<96, 256>>>();
    final_reduce<<<1, 32>>>((float*)d_out);
}